// round 1
// baseline (speedup 1.0000x reference)
#include <cuda_runtime.h>
#include <cstdint>

// Problem constants
#define BATCH   2
#define S_LEN   2048
#define D_MODEL 1024
#define NH      16
#define HD      64
#define WINDOW  256

#define TOKENS  (BATCH * S_LEN)          // 4096
#define OUT_ELEMS ((size_t)TOKENS * D_MODEL)  // 4194304

// Scratch (device globals: allocation-free rule)
__device__ float g_q [BATCH * NH * S_LEN * HD];        // [B,H,S,hd]
__device__ float g_kv[BATCH * 2 * NH * S_LEN * HD];    // [B,2,H,S,hd] == present
__device__ float g_a [TOKENS * D_MODEL];               // merged-head attn out [B,S,D]

// ---------------------------------------------------------------------------
// 128x128x8 register-tiled fp32 GEMM. C = A(MxK) @ B(KxN) + bias(N)
// MODE 1: QKV epilogue (scatter into g_q / g_kv). MODE 0: plain, A = g_a.
// ---------------------------------------------------------------------------
template <int MODE>
__global__ __launch_bounds__(256) void sgemm_k(const float* __restrict__ A,
                                               const float* __restrict__ B,
                                               const float* __restrict__ bias,
                                               float* __restrict__ C,
                                               int M, int N, int K)
{
    __shared__ float As[8][132];
    __shared__ float Bs[8][132];

    const float* Ause = (MODE == 0) ? (const float*)g_a : A;

    const int tid = threadIdx.x;
    const int tx = tid & 15;       // 0..15 -> 8 cols each
    const int ty = tid >> 4;       // 0..15 -> 8 rows each
    const int m0 = blockIdx.y * 128;
    const int n0 = blockIdx.x * 128;

    const int arow = tid >> 1;          // 0..127
    const int acol = (tid & 1) * 4;     // 0 or 4
    const int brow = tid >> 5;          // 0..7
    const int bcol = (tid & 31) * 4;    // 0..124

    const float* Aptr = Ause + (size_t)(m0 + arow) * K + acol;
    const float* Bptr = B + (size_t)brow * N + n0 + bcol;

    float acc[8][8];
#pragma unroll
    for (int i = 0; i < 8; i++)
#pragma unroll
        for (int j = 0; j < 8; j++) acc[i][j] = 0.f;

    for (int k0 = 0; k0 < K; k0 += 8) {
        float4 av = *(const float4*)(Aptr + k0);
        float4 bv = *(const float4*)(Bptr + (size_t)k0 * N);
        As[acol + 0][arow] = av.x;
        As[acol + 1][arow] = av.y;
        As[acol + 2][arow] = av.z;
        As[acol + 3][arow] = av.w;
        *(float4*)&Bs[brow][bcol] = bv;
        __syncthreads();

#pragma unroll
        for (int k = 0; k < 8; k++) {
            float4 a0 = *(const float4*)&As[k][ty * 8];
            float4 a1 = *(const float4*)&As[k][ty * 8 + 4];
            float4 b0 = *(const float4*)&Bs[k][tx * 8];
            float4 b1 = *(const float4*)&Bs[k][tx * 8 + 4];
            float a[8] = {a0.x, a0.y, a0.z, a0.w, a1.x, a1.y, a1.z, a1.w};
            float b[8] = {b0.x, b0.y, b0.z, b0.w, b1.x, b1.y, b1.z, b1.w};
#pragma unroll
            for (int i = 0; i < 8; i++)
#pragma unroll
                for (int j = 0; j < 8; j++) acc[i][j] += a[i] * b[j];
        }
        __syncthreads();
    }

    if (MODE == 0) {
#pragma unroll
        for (int i = 0; i < 8; i++) {
            const int gm = m0 + ty * 8 + i;
#pragma unroll
            for (int j = 0; j < 8; j += 4) {
                const int gn = n0 + tx * 8 + j;
                float4 r;
                r.x = acc[i][j + 0] + bias[gn + 0];
                r.y = acc[i][j + 1] + bias[gn + 1];
                r.z = acc[i][j + 2] + bias[gn + 2];
                r.w = acc[i][j + 3] + bias[gn + 3];
                *(float4*)&C[(size_t)gm * N + gn] = r;
            }
        }
    } else {
        // QKV scatter: f<1024 -> Q, <2048 -> K, else V
#pragma unroll
        for (int i = 0; i < 8; i++) {
            const int t = m0 + ty * 8 + i;
            const int bb = t >> 11;          // /2048
            const int s  = t & 2047;
#pragma unroll
            for (int j = 0; j < 8; j++) {
                const int f = n0 + tx * 8 + j;
                const float v = acc[i][j] + bias[f];
                const int sec = f >> 10;
                const int fr  = f & 1023;
                const int h   = fr >> 6;
                const int d   = fr & 63;
                if (sec == 0)
                    g_q[(((size_t)bb * NH + h) * S_LEN + s) * HD + d] = v;
                else
                    g_kv[((((size_t)bb * 2 + (sec - 1)) * NH + h) * S_LEN + s) * HD + d] = v;
            }
        }
    }
}

// ---------------------------------------------------------------------------
// Sliding-window attention. One block per (b, h, 64-query tile).
// Scores the full [64 x 320] window into smem, softmax, PV, write merged-head.
// ---------------------------------------------------------------------------
#define ATTN_SMEM_FLOATS (2 * 64 * 65 + 64 * 321 + 64)
#define ATTN_SMEM_BYTES  (ATTN_SMEM_FLOATS * 4)

__global__ __launch_bounds__(256) void attn_k()
{
    extern __shared__ float sm[];
    float (*Qs)[65]  = (float(*)[65])sm;                    // 64x65
    float (*Ks)[65]  = (float(*)[65])(sm + 64 * 65);        // 64x65 (K then V)
    float (*Ss)[321] = (float(*)[321])(sm + 2 * 64 * 65);   // 64x321 (320 used)
    float* rinv      = sm + 2 * 64 * 65 + 64 * 321;

    const int bid = blockIdx.x;
    const int qt = bid & 31;
    const int h  = (bid >> 5) & 15;
    const int b  = bid >> 9;
    const int qs = qt * 64;

    const int tid = threadIdx.x;
    const int tx = tid & 15;
    const int ty = tid >> 4;
    const float scale = 0.125f;  // 1/sqrt(64)

    const float* Qg = g_q  + (((size_t)b * NH + h) * S_LEN) * HD;
    const float* Kg = g_kv + ((((size_t)b * 2 + 0) * NH + h) * S_LEN) * HD;
    const float* Vg = g_kv + ((((size_t)b * 2 + 1) * NH + h) * S_LEN) * HD;

    // load Q tile (pre-scaled)
    for (int idx = tid; idx < 64 * 64; idx += 256) {
        const int i = idx >> 6, d = idx & 63;
        Qs[i][d] = Qg[(size_t)(qs + i) * HD + d] * scale;
    }

    // ---- score phase: 5 key tiles covering [qs-256, qs+64) ----
    for (int kt = 0; kt < 5; kt++) {
        const int ks = qs - 256 + kt * 64;
        if (ks + 64 <= 0) {  // entirely out of range
            for (int idx = tid; idx < 64 * 64; idx += 256)
                Ss[idx >> 6][kt * 64 + (idx & 63)] = -1e30f;
            continue;
        }
        __syncthreads();  // Q visible / prev tile's compute done before reload
        for (int idx = tid; idx < 64 * 64; idx += 256) {
            const int j = idx >> 6, d = idx & 63;
            const int gj = ks + j;
            Ks[j][d] = (gj >= 0) ? Kg[(size_t)gj * HD + d] : 0.f;
        }
        __syncthreads();

        float s[4][4];
#pragma unroll
        for (int r = 0; r < 4; r++)
#pragma unroll
            for (int c = 0; c < 4; c++) s[r][c] = 0.f;
        const int i0 = ty * 4, j0 = tx * 4;
#pragma unroll 8
        for (int d = 0; d < 64; d++) {
            float q[4], kk[4];
#pragma unroll
            for (int r = 0; r < 4; r++) q[r] = Qs[i0 + r][d];
#pragma unroll
            for (int c = 0; c < 4; c++) kk[c] = Ks[j0 + c][d];
#pragma unroll
            for (int r = 0; r < 4; r++)
#pragma unroll
                for (int c = 0; c < 4; c++) s[r][c] += q[r] * kk[c];
        }
#pragma unroll
        for (int r = 0; r < 4; r++) {
            const int gi = qs + i0 + r;
#pragma unroll
            for (int c = 0; c < 4; c++) {
                const int gj = ks + j0 + c;
                const bool ok = (gj >= 0) && (gj <= gi) && (gj > gi - WINDOW);
                Ss[i0 + r][kt * 64 + j0 + c] = ok ? s[r][c] : -1e30f;
            }
        }
    }
    __syncthreads();

    // ---- softmax over 320 cols (unnormalized exp; 1/sum folded into PV out) ----
    if (tid < 64) {
        float mx = -1e30f;
        for (int c = 0; c < 320; c++) mx = fmaxf(mx, Ss[tid][c]);
        float sum = 0.f;
        for (int c = 0; c < 320; c++) {
            const float e = __expf(Ss[tid][c] - mx);
            Ss[tid][c] = e;
            sum += e;
        }
        rinv[tid] = 1.f / sum;
    }

    // ---- PV phase ----
    float o[4][4];
#pragma unroll
    for (int r = 0; r < 4; r++)
#pragma unroll
        for (int c = 0; c < 4; c++) o[r][c] = 0.f;
    const int i0 = ty * 4, d0 = tx * 4;

    for (int kt = 0; kt < 5; kt++) {
        const int ks = qs - 256 + kt * 64;
        if (ks + 64 <= 0) continue;
        __syncthreads();  // softmax done / prev V compute done
        for (int idx = tid; idx < 64 * 64; idx += 256) {
            const int j = idx >> 6, d = idx & 63;
            const int gj = ks + j;
            Ks[j][d] = (gj >= 0) ? Vg[(size_t)gj * HD + d] : 0.f;
        }
        __syncthreads();
#pragma unroll 8
        for (int j = 0; j < 64; j++) {
            float p[4], v[4];
#pragma unroll
            for (int r = 0; r < 4; r++) p[r] = Ss[i0 + r][kt * 64 + j];
#pragma unroll
            for (int c = 0; c < 4; c++) v[c] = Ks[j][d0 + c];
#pragma unroll
            for (int r = 0; r < 4; r++)
#pragma unroll
                for (int c = 0; c < 4; c++) o[r][c] += p[r] * v[c];
        }
    }

    // write merged-head A [B,S,D]
#pragma unroll
    for (int r = 0; r < 4; r++) {
        const float ri = rinv[i0 + r];
#pragma unroll
        for (int c = 0; c < 4; c++) {
            g_a[((size_t)b * S_LEN + qs + i0 + r) * D_MODEL + h * HD + d0 + c] =
                o[r][c] * ri;
        }
    }
}

// ---------------------------------------------------------------------------
extern "C" void kernel_launch(void* const* d_in, const int* in_sizes, int n_in,
                              void* d_out, int out_size)
{
    const float* x      = (const float*)d_in[0];
    const float* w_attn = (const float*)d_in[1];
    const float* b_attn = (const float*)d_in[2];
    const float* w_proj = (const float*)d_in[3];
    const float* b_proj = (const float*)d_in[4];
    float* out = (float*)d_out;

    cudaFuncSetAttribute(attn_k, cudaFuncAttributeMaxDynamicSharedMemorySize,
                         ATTN_SMEM_BYTES);

    // 1) fused QKV projection, scattered into g_q / g_kv (present layout)
    {
        dim3 grid(3 * D_MODEL / 128, TOKENS / 128);  // (24, 32)
        sgemm_k<1><<<grid, 256>>>(x, w_attn, b_attn, nullptr,
                                  TOKENS, 3 * D_MODEL, D_MODEL);
    }

    // 2) sliding-window attention -> g_a
    attn_k<<<BATCH * NH * (S_LEN / 64), 256, ATTN_SMEM_BYTES>>>();

    // 3) output projection -> d_out[0 : 4194304]
    {
        dim3 grid(D_MODEL / 128, TOKENS / 128);      // (8, 32)
        sgemm_k<0><<<grid, 256>>>(nullptr, w_proj, b_proj, out,
                                  TOKENS, D_MODEL, D_MODEL);
    }

    // 4) present (k,v stack) if it is part of the flattened output
    if ((size_t)out_size > OUT_ELEMS) {
        cudaMemcpyFromSymbolAsync(out + OUT_ELEMS, g_kv, sizeof(g_kv), 0,
                                  cudaMemcpyDeviceToDevice, 0);
    }
}

// round 4
// speedup vs baseline: 1.5817x; 1.5817x over previous
#include <cuda_runtime.h>
#include <cuda_bf16.h>
#include <cstdint>

// Problem constants
#define BATCH   2
#define S_LEN   2048
#define D_MODEL 1024
#define NH      16
#define HD      64
#define WINDOW  256
#define TOKENS  (BATCH * S_LEN)               // 4096
#define OUT_ELEMS ((size_t)TOKENS * D_MODEL)  // 4194304
#define KEFF    3072                          // 3 * 1024 (hi/hi/lo split along K)
#define NCHUNK  48                            // KEFF / 64

// ---------------- device scratch (allocation-free rule) ----------------
__device__ __align__(128) float g_q [BATCH * NH * S_LEN * HD];
__device__ __align__(128) float g_kv[BATCH * 2 * NH * S_LEN * HD];   // == present
__device__ __align__(128) float g_a [TOKENS * D_MODEL];
__device__ __align__(128) __nv_bfloat16 g_xhat[(size_t)TOKENS * KEFF];      // [A_hi|A_hi|A_lo]
__device__ __align__(128) __nv_bfloat16 g_ahat[(size_t)TOKENS * KEFF];
__device__ __align__(128) __nv_bfloat16 g_wat [(size_t)3 * D_MODEL * KEFF]; // W^T split [B_hi|B_lo|B_hi]
__device__ __align__(128) __nv_bfloat16 g_wpt [(size_t)D_MODEL * KEFF];

// ---------------- helpers ----------------
__device__ __forceinline__ uint32_t smem_u32(const void* p) {
    uint32_t a;
    asm("{ .reg .u64 t; cvta.to.shared.u64 t, %1; cvt.u32.u64 %0, t; }" : "=r"(a) : "l"(p));
    return a;
}
__device__ __forceinline__ void cp16(uint32_t saddr, const void* g) {
    asm volatile("cp.async.cg.shared.global [%0], [%1], 16;" :: "r"(saddr), "l"(g));
}
#define CP_COMMIT() asm volatile("cp.async.commit_group;" ::: "memory")
#define CP_WAIT1()  asm volatile("cp.async.wait_group 1;" ::: "memory")

__device__ __forceinline__ void ldmx4(uint32_t* r, uint32_t addr) {
    asm volatile("ldmatrix.sync.aligned.m8n8.x4.shared.b16 {%0,%1,%2,%3}, [%4];"
                 : "=r"(r[0]), "=r"(r[1]), "=r"(r[2]), "=r"(r[3]) : "r"(addr));
}
__device__ __forceinline__ void mma16816(float* c, const uint32_t* a, const uint32_t* b) {
    asm volatile(
        "mma.sync.aligned.m16n8k16.row.col.f32.bf16.bf16.f32 "
        "{%0,%1,%2,%3}, {%4,%5,%6,%7}, {%8,%9}, {%0,%1,%2,%3};"
        : "+f"(c[0]), "+f"(c[1]), "+f"(c[2]), "+f"(c[3])
        : "r"(a[0]), "r"(a[1]), "r"(a[2]), "r"(a[3]), "r"(b[0]), "r"(b[1]));
}

// ---------------- split conversion kernels ----------------
// fp32 [M,1024] -> bf16 [M,3072] segments [hi | hi | lo]
__global__ void convA_k(const float* __restrict__ A, __nv_bfloat16* __restrict__ O, int total)
{
    int idx = blockIdx.x * blockDim.x + threadIdx.x;
    if (idx >= total) return;
    int m = idx >> 10, k = idx & 1023;
    float v = A[idx];
    __nv_bfloat16 hi = __float2bfloat16(v);
    __nv_bfloat16 lo = __float2bfloat16(v - __bfloat162float(hi));
    __nv_bfloat16* row = O + (size_t)m * KEFF;
    row[k] = hi; row[1024 + k] = hi; row[2048 + k] = lo;
}
// W fp32 [1024, N] row-major -> Bt bf16 [N, 3072] segments [hi | lo | hi] (transpose)
__global__ void convBt_k(const float* __restrict__ W, __nv_bfloat16* __restrict__ O, int N)
{
    __shared__ float tile[32][33];
    int k0 = blockIdx.y * 32, n0 = blockIdx.x * 32;
    int tx = threadIdx.x, ty = threadIdx.y;
    tile[ty][tx] = W[(size_t)(k0 + ty) * N + n0 + tx];
    __syncthreads();
    float v = tile[tx][ty];
    __nv_bfloat16 hi = __float2bfloat16(v);
    __nv_bfloat16 lo = __float2bfloat16(v - __bfloat162float(hi));
    __nv_bfloat16* row = O + (size_t)(n0 + ty) * KEFF;
    int k = k0 + tx;
    row[k] = hi; row[1024 + k] = lo; row[2048 + k] = hi;
}

// ---------------- mma.sync GEMM: C(4096, N) = Ahat(M,3072) . Bt(N,3072)^T ----------------
// Block 128x128, K-chunk 64, 8 warps (2Mx4N), warp tile 64x32, double-buffered cp.async.
// Smem rows padded to 144B for conflict-free ldmatrix.
#define TILE_BYTES  18432         // 128 rows * 144B
#define BUF_BYTES   36864         // A + B
#define GEMM_SMEM   73728         // 2 buffers

template<int MODE>
__global__ __launch_bounds__(256, 1) void gemm_mma(const __nv_bfloat16* __restrict__ A,
                                                   const __nv_bfloat16* __restrict__ Bt,
                                                   const float* __restrict__ bias,
                                                   float* __restrict__ C)
{
    extern __shared__ char smem[];
    const uint32_t sb = smem_u32(smem);
    const int tid = threadIdx.x;
    const int wid = tid >> 5, lid = tid & 31;
    const int m0 = blockIdx.y * 128, n0 = blockIdx.x * 128;
    const int mbase = (wid & 1) * 64;     // warp M offset
    const int nbase = (wid >> 1) * 32;    // warp N offset

    const char* Abase = (const char*)(A  + (size_t)m0 * KEFF);
    const char* Bbase = (const char*)(Bt + (size_t)n0 * KEFF);

    float acc[4][4][4];
#pragma unroll
    for (int mt = 0; mt < 4; mt++)
#pragma unroll
        for (int nt = 0; nt < 4; nt++)
#pragma unroll
            for (int i = 0; i < 4; i++) acc[mt][nt][i] = 0.f;

#define PREFETCH(c, buf)                                                          \
    {                                                                             \
        const size_t kbyte = (size_t)(c) * 128;                                   \
        const uint32_t abuf = sb + (buf) * BUF_BYTES;                             \
        const uint32_t bbuf = abuf + TILE_BYTES;                                  \
        _Pragma("unroll")                                                         \
        for (int i = 0; i < 4; i++) {                                             \
            int idx = tid + i * 256;                                              \
            int row = idx >> 3, seg = idx & 7;                                    \
            uint32_t so = row * 144 + seg * 16;                                   \
            cp16(abuf + so, Abase + (size_t)row * (KEFF * 2) + kbyte + seg * 16); \
            cp16(bbuf + so, Bbase + (size_t)row * (KEFF * 2) + kbyte + seg * 16); \
        }                                                                         \
    }

    PREFETCH(0, 0); CP_COMMIT();
    PREFETCH(1, 1); CP_COMMIT();

    for (int c = 0; c < NCHUNK; c++) {
        CP_WAIT1();
        __syncthreads();
        const uint32_t abuf = sb + (c & 1) * BUF_BYTES;
        const uint32_t bbuf = abuf + TILE_BYTES;
#pragma unroll
        for (int ks = 0; ks < 4; ks++) {
            const int k0 = ks * 16;
            uint32_t ar[4][4];
            uint32_t br[4][2];
#pragma unroll
            for (int mt = 0; mt < 4; mt++) {
                uint32_t addr = abuf +
                    (uint32_t)((mbase + mt * 16 + ((lid >> 3) & 1) * 8 + (lid & 7)) * 144
                               + (k0 + (lid >> 4) * 8) * 2);
                ldmx4(ar[mt], addr);
            }
#pragma unroll
            for (int p = 0; p < 2; p++) {
                uint32_t r[4];
                uint32_t addr = bbuf +
                    (uint32_t)((nbase + p * 16 + ((lid >> 4) & 1) * 8 + (lid & 7)) * 144
                               + (k0 + ((lid >> 3) & 1) * 8) * 2);
                ldmx4(r, addr);
                br[p * 2][0] = r[0]; br[p * 2][1] = r[1];
                br[p * 2 + 1][0] = r[2]; br[p * 2 + 1][1] = r[3];
            }
#pragma unroll
            for (int mt = 0; mt < 4; mt++)
#pragma unroll
                for (int nt = 0; nt < 4; nt++)
                    mma16816(acc[mt][nt], ar[mt], br[nt]);
        }
        __syncthreads();
        if (c + 2 < NCHUNK) PREFETCH(c + 2, c & 1);
        CP_COMMIT();
    }
#undef PREFETCH

    // ---- epilogue ----
    const int lrow = lid >> 2;           // 0..7
    const int lcol = (lid & 3) * 2;      // 0,2,4,6
#pragma unroll
    for (int mt = 0; mt < 4; mt++) {
        const int gm = m0 + mbase + mt * 16 + lrow;
#pragma unroll
        for (int nt = 0; nt < 4; nt++) {
            const int gn = n0 + nbase + nt * 8 + lcol;
            if (MODE == 0) {
                const float b0 = bias[gn], b1 = bias[gn + 1];
                float2 v0 = {acc[mt][nt][0] + b0, acc[mt][nt][1] + b1};
                float2 v1 = {acc[mt][nt][2] + b0, acc[mt][nt][3] + b1};
                *(float2*)&C[(size_t)gm * D_MODEL + gn] = v0;
                *(float2*)&C[(size_t)(gm + 8) * D_MODEL + gn] = v1;
            } else {
#pragma unroll
                for (int e = 0; e < 4; e++) {
                    const int row = gm + (e >> 1) * 8;
                    const int f   = gn + (e & 1);
                    const float v = acc[mt][nt][e] + bias[f];
                    const int bb = row >> 11, s = row & 2047;
                    const int sec = f >> 10, fr = f & 1023;
                    const int h = fr >> 6, dd = fr & 63;
                    if (sec == 0)
                        g_q[(((size_t)bb * NH + h) * S_LEN + s) * HD + dd] = v;
                    else
                        g_kv[((((size_t)bb * 2 + (sec - 1)) * NH + h) * S_LEN + s) * HD + dd] = v;
                }
            }
        }
    }
}

// ---------------- sliding-window attention (unchanged) ----------------
#define ATTN_SMEM_FLOATS (2 * 64 * 65 + 64 * 321 + 64)
#define ATTN_SMEM_BYTES  (ATTN_SMEM_FLOATS * 4)

__global__ __launch_bounds__(256) void attn_k()
{
    extern __shared__ float sm[];
    float (*Qs)[65]  = (float(*)[65])sm;
    float (*Ks)[65]  = (float(*)[65])(sm + 64 * 65);
    float (*Ss)[321] = (float(*)[321])(sm + 2 * 64 * 65);
    float* rinv      = sm + 2 * 64 * 65 + 64 * 321;

    const int bid = blockIdx.x;
    const int qt = bid & 31;
    const int h  = (bid >> 5) & 15;
    const int b  = bid >> 9;
    const int qs = qt * 64;

    const int tid = threadIdx.x;
    const int tx = tid & 15;
    const int ty = tid >> 4;
    const float scale = 0.125f;

    const float* Qg = g_q  + (((size_t)b * NH + h) * S_LEN) * HD;
    const float* Kg = g_kv + ((((size_t)b * 2 + 0) * NH + h) * S_LEN) * HD;
    const float* Vg = g_kv + ((((size_t)b * 2 + 1) * NH + h) * S_LEN) * HD;

    for (int idx = tid; idx < 64 * 64; idx += 256) {
        const int i = idx >> 6, d = idx & 63;
        Qs[i][d] = Qg[(size_t)(qs + i) * HD + d] * scale;
    }

    for (int kt = 0; kt < 5; kt++) {
        const int ks = qs - 256 + kt * 64;
        if (ks + 64 <= 0) {
            for (int idx = tid; idx < 64 * 64; idx += 256)
                Ss[idx >> 6][kt * 64 + (idx & 63)] = -1e30f;
            continue;
        }
        __syncthreads();
        for (int idx = tid; idx < 64 * 64; idx += 256) {
            const int j = idx >> 6, d = idx & 63;
            const int gj = ks + j;
            Ks[j][d] = (gj >= 0) ? Kg[(size_t)gj * HD + d] : 0.f;
        }
        __syncthreads();

        float s[4][4];
#pragma unroll
        for (int r = 0; r < 4; r++)
#pragma unroll
            for (int c = 0; c < 4; c++) s[r][c] = 0.f;
        const int i0 = ty * 4, j0 = tx * 4;
#pragma unroll 8
        for (int d = 0; d < 64; d++) {
            float q[4], kk[4];
#pragma unroll
            for (int r = 0; r < 4; r++) q[r] = Qs[i0 + r][d];
#pragma unroll
            for (int c = 0; c < 4; c++) kk[c] = Ks[j0 + c][d];
#pragma unroll
            for (int r = 0; r < 4; r++)
#pragma unroll
                for (int c = 0; c < 4; c++) s[r][c] += q[r] * kk[c];
        }
#pragma unroll
        for (int r = 0; r < 4; r++) {
            const int gi = qs + i0 + r;
#pragma unroll
            for (int c = 0; c < 4; c++) {
                const int gj = ks + j0 + c;
                const bool ok = (gj >= 0) && (gj <= gi) && (gj > gi - WINDOW);
                Ss[i0 + r][kt * 64 + j0 + c] = ok ? s[r][c] : -1e30f;
            }
        }
    }
    __syncthreads();

    if (tid < 64) {
        float mx = -1e30f;
        for (int c = 0; c < 320; c++) mx = fmaxf(mx, Ss[tid][c]);
        float sum = 0.f;
        for (int c = 0; c < 320; c++) {
            const float e = __expf(Ss[tid][c] - mx);
            Ss[tid][c] = e;
            sum += e;
        }
        rinv[tid] = 1.f / sum;
    }

    float o[4][4];
#pragma unroll
    for (int r = 0; r < 4; r++)
#pragma unroll
        for (int c = 0; c < 4; c++) o[r][c] = 0.f;
    const int i0 = ty * 4, d0 = tx * 4;

    for (int kt = 0; kt < 5; kt++) {
        const int ks = qs - 256 + kt * 64;
        if (ks + 64 <= 0) continue;
        __syncthreads();
        for (int idx = tid; idx < 64 * 64; idx += 256) {
            const int j = idx >> 6, d = idx & 63;
            const int gj = ks + j;
            Ks[j][d] = (gj >= 0) ? Vg[(size_t)gj * HD + d] : 0.f;
        }
        __syncthreads();
#pragma unroll 8
        for (int j = 0; j < 64; j++) {
            float p[4], v[4];
#pragma unroll
            for (int r = 0; r < 4; r++) p[r] = Ss[i0 + r][kt * 64 + j];
#pragma unroll
            for (int c = 0; c < 4; c++) v[c] = Ks[j][d0 + c];
#pragma unroll
            for (int r = 0; r < 4; r++)
#pragma unroll
                for (int c = 0; c < 4; c++) o[r][c] += p[r] * v[c];
        }
    }

#pragma unroll
    for (int r = 0; r < 4; r++) {
        const float ri = rinv[i0 + r];
#pragma unroll
        for (int c = 0; c < 4; c++) {
            g_a[((size_t)b * S_LEN + qs + i0 + r) * D_MODEL + h * HD + d0 + c] =
                o[r][c] * ri;
        }
    }
}

// ---------------------------------------------------------------------------
extern "C" void kernel_launch(void* const* d_in, const int* in_sizes, int n_in,
                              void* d_out, int out_size)
{
    const float* x      = (const float*)d_in[0];
    const float* w_attn = (const float*)d_in[1];
    const float* b_attn = (const float*)d_in[2];
    const float* w_proj = (const float*)d_in[3];
    const float* b_proj = (const float*)d_in[4];
    float* out = (float*)d_out;

    cudaFuncSetAttribute(attn_k, cudaFuncAttributeMaxDynamicSharedMemorySize, ATTN_SMEM_BYTES);
    cudaFuncSetAttribute(gemm_mma<0>, cudaFuncAttributeMaxDynamicSharedMemorySize, GEMM_SMEM);
    cudaFuncSetAttribute(gemm_mma<1>, cudaFuncAttributeMaxDynamicSharedMemorySize, GEMM_SMEM);

    __nv_bfloat16 *xhat, *ahat, *wat, *wpt;
    cudaGetSymbolAddress((void**)&xhat, g_xhat);
    cudaGetSymbolAddress((void**)&ahat, g_ahat);
    cudaGetSymbolAddress((void**)&wat,  g_wat);
    cudaGetSymbolAddress((void**)&wpt,  g_wpt);
    float* ga; cudaGetSymbolAddress((void**)&ga, g_a);

    // 1) split conversions of inputs
    convA_k<<<(TOKENS * 1024 + 255) / 256, 256>>>(x, xhat, TOKENS * 1024);
    {
        dim3 blk(32, 32);
        convBt_k<<<dim3(3 * D_MODEL / 32, D_MODEL / 32), blk>>>(w_attn, wat, 3 * D_MODEL);
        convBt_k<<<dim3(D_MODEL / 32, D_MODEL / 32),     blk>>>(w_proj, wpt, D_MODEL);
    }

    // 2) QKV projection on tensor cores -> g_q / g_kv (present layout)
    gemm_mma<1><<<dim3(3 * D_MODEL / 128, TOKENS / 128), 256, GEMM_SMEM>>>(
        xhat, wat, b_attn, nullptr);

    // 3) sliding-window attention -> g_a
    attn_k<<<BATCH * NH * (S_LEN / 64), 256, ATTN_SMEM_BYTES>>>();

    // 4) split-convert attention output, then output projection -> d_out
    convA_k<<<(TOKENS * 1024 + 255) / 256, 256>>>(ga, ahat, TOKENS * 1024);
    gemm_mma<0><<<dim3(D_MODEL / 128, TOKENS / 128), 256, GEMM_SMEM>>>(
        ahat, wpt, b_proj, out);

    // 5) present (k,v stack) tail of the flattened output
    if ((size_t)out_size > OUT_ELEMS) {
        cudaMemcpyFromSymbolAsync(out + OUT_ELEMS, g_kv, sizeof(g_kv), 0,
                                  cudaMemcpyDeviceToDevice, 0);
    }
}

// round 5
// speedup vs baseline: 1.6386x; 1.0360x over previous
#include <cuda_runtime.h>
#include <cuda_bf16.h>
#include <cstdint>

// Problem constants
#define BATCH   2
#define S_LEN   2048
#define D_MODEL 1024
#define NH      16
#define HD      64
#define WINDOW  256
#define TOKENS  (BATCH * S_LEN)               // 4096
#define OUT_ELEMS ((size_t)TOKENS * D_MODEL)  // 4194304
#define KEFF    3072                          // 3 * 1024 (hi/hi/lo split along K)
#define NCHUNK  48                            // KEFF / 64

// ---------------- device scratch (allocation-free rule) ----------------
__device__ __align__(128) float g_q [BATCH * NH * S_LEN * HD];
__device__ __align__(128) __nv_bfloat16 g_xhat[(size_t)TOKENS * KEFF];      // [A_hi|A_hi|A_lo]
__device__ __align__(128) __nv_bfloat16 g_ahat[(size_t)TOKENS * KEFF];
__device__ __align__(128) __nv_bfloat16 g_wat [(size_t)3 * D_MODEL * KEFF]; // W^T split [B_hi|B_lo|B_hi]
__device__ __align__(128) __nv_bfloat16 g_wpt [(size_t)D_MODEL * KEFF];

// ---------------- helpers ----------------
__device__ __forceinline__ uint32_t smem_u32(const void* p) {
    uint32_t a;
    asm("{ .reg .u64 t; cvta.to.shared.u64 t, %1; cvt.u32.u64 %0, t; }" : "=r"(a) : "l"(p));
    return a;
}
__device__ __forceinline__ void cp16(uint32_t saddr, const void* g) {
    asm volatile("cp.async.cg.shared.global [%0], [%1], 16;" :: "r"(saddr), "l"(g));
}
#define CP_COMMIT() asm volatile("cp.async.commit_group;" ::: "memory")
#define CP_WAIT1()  asm volatile("cp.async.wait_group 1;" ::: "memory")
#define CP_WAIT0()  asm volatile("cp.async.wait_group 0;" ::: "memory")

__device__ __forceinline__ void ldmx4(uint32_t* r, uint32_t addr) {
    asm volatile("ldmatrix.sync.aligned.m8n8.x4.shared.b16 {%0,%1,%2,%3}, [%4];"
                 : "=r"(r[0]), "=r"(r[1]), "=r"(r[2]), "=r"(r[3]) : "r"(addr));
}
__device__ __forceinline__ void mma16816(float* c, const uint32_t* a, const uint32_t* b) {
    asm volatile(
        "mma.sync.aligned.m16n8k16.row.col.f32.bf16.bf16.f32 "
        "{%0,%1,%2,%3}, {%4,%5,%6,%7}, {%8,%9}, {%0,%1,%2,%3};"
        : "+f"(c[0]), "+f"(c[1]), "+f"(c[2]), "+f"(c[3])
        : "r"(a[0]), "r"(a[1]), "r"(a[2]), "r"(a[3]), "r"(b[0]), "r"(b[1]));
}

// ---------------- split conversion kernels ----------------
// fp32 [M,1024] -> bf16 [M,3072] segments [hi | hi | lo]
__global__ void convA_k(const float* __restrict__ A, __nv_bfloat16* __restrict__ O, int total)
{
    int idx = blockIdx.x * blockDim.x + threadIdx.x;
    if (idx >= total) return;
    int m = idx >> 10, k = idx & 1023;
    float v = A[idx];
    __nv_bfloat16 hi = __float2bfloat16(v);
    __nv_bfloat16 lo = __float2bfloat16(v - __bfloat162float(hi));
    __nv_bfloat16* row = O + (size_t)m * KEFF;
    row[k] = hi; row[1024 + k] = hi; row[2048 + k] = lo;
}
// W fp32 [1024, N] row-major -> Bt bf16 [N, 3072] segments [hi | lo | hi] (transpose)
__global__ void convBt_k(const float* __restrict__ W, __nv_bfloat16* __restrict__ O, int N)
{
    __shared__ float tile[32][33];
    int k0 = blockIdx.y * 32, n0 = blockIdx.x * 32;
    int tx = threadIdx.x, ty = threadIdx.y;
    tile[ty][tx] = W[(size_t)(k0 + ty) * N + n0 + tx];
    __syncthreads();
    float v = tile[tx][ty];
    __nv_bfloat16 hi = __float2bfloat16(v);
    __nv_bfloat16 lo = __float2bfloat16(v - __bfloat162float(hi));
    __nv_bfloat16* row = O + (size_t)(n0 + ty) * KEFF;
    int k = k0 + tx;
    row[k] = hi; row[1024 + k] = lo; row[2048 + k] = hi;
}

// ---------------- mma.sync GEMM: C(4096, N) = Ahat(M,3072) . Bt(N,3072)^T ----------------
// Block 128x128, K-chunk 64, 8 warps (2Mx4N), warp tile 64x32.
// 3-stage cp.async pipeline, ONE __syncthreads per chunk.
// Smem rows padded to 144B for conflict-free ldmatrix.
#define TILE_BYTES  18432         // 128 rows * 144B
#define BUF_BYTES   36864         // A + B
#define GEMM_SMEM   110592        // 3 buffers

template<int MODE>
__global__ __launch_bounds__(256, 1) void gemm_mma(const __nv_bfloat16* __restrict__ A,
                                                   const __nv_bfloat16* __restrict__ Bt,
                                                   const float* __restrict__ bias,
                                                   float* __restrict__ C,
                                                   float* __restrict__ KV)
{
    extern __shared__ char smem[];
    const uint32_t sb = smem_u32(smem);
    const int tid = threadIdx.x;
    const int wid = tid >> 5, lid = tid & 31;
    const int m0 = blockIdx.y * 128, n0 = blockIdx.x * 128;
    const int mbase = (wid & 1) * 64;     // warp M offset
    const int nbase = (wid >> 1) * 32;    // warp N offset

    const char* Abase = (const char*)(A  + (size_t)m0 * KEFF);
    const char* Bbase = (const char*)(Bt + (size_t)n0 * KEFF);

    float acc[4][4][4];
#pragma unroll
    for (int mt = 0; mt < 4; mt++)
#pragma unroll
        for (int nt = 0; nt < 4; nt++)
#pragma unroll
            for (int i = 0; i < 4; i++) acc[mt][nt][i] = 0.f;

#define PREFETCH(c, buf)                                                          \
    {                                                                             \
        const size_t kbyte = (size_t)(c) * 128;                                   \
        const uint32_t abuf = sb + (buf) * BUF_BYTES;                             \
        const uint32_t bbuf = abuf + TILE_BYTES;                                  \
        _Pragma("unroll")                                                         \
        for (int i = 0; i < 4; i++) {                                             \
            int idx = tid + i * 256;                                              \
            int row = idx >> 3, seg = idx & 7;                                    \
            uint32_t so = row * 144 + seg * 16;                                   \
            cp16(abuf + so, Abase + (size_t)row * (KEFF * 2) + kbyte + seg * 16); \
            cp16(bbuf + so, Bbase + (size_t)row * (KEFF * 2) + kbyte + seg * 16); \
        }                                                                         \
    }

    PREFETCH(0, 0); CP_COMMIT();
    PREFETCH(1, 1); CP_COMMIT();

    int buf = 0;
    for (int c = 0; c < NCHUNK; c++) {
        if (c == NCHUNK - 1) { CP_WAIT0(); } else { CP_WAIT1(); }
        __syncthreads();   // chunk c landed; all warps done consuming chunk c-1
        if (c + 2 < NCHUNK) {
            int nbuf = buf + 2; if (nbuf >= 3) nbuf -= 3;
            PREFETCH(c + 2, nbuf);
            CP_COMMIT();
        }
        const uint32_t abuf = sb + buf * BUF_BYTES;
        const uint32_t bbuf = abuf + TILE_BYTES;
#pragma unroll
        for (int ks = 0; ks < 4; ks++) {
            const int k0 = ks * 16;
            uint32_t ar[4][4];
            uint32_t br[4][2];
#pragma unroll
            for (int mt = 0; mt < 4; mt++) {
                uint32_t addr = abuf +
                    (uint32_t)((mbase + mt * 16 + ((lid >> 3) & 1) * 8 + (lid & 7)) * 144
                               + (k0 + (lid >> 4) * 8) * 2);
                ldmx4(ar[mt], addr);
            }
#pragma unroll
            for (int p = 0; p < 2; p++) {
                uint32_t r[4];
                uint32_t addr = bbuf +
                    (uint32_t)((nbase + p * 16 + ((lid >> 4) & 1) * 8 + (lid & 7)) * 144
                               + (k0 + ((lid >> 3) & 1) * 8) * 2);
                ldmx4(r, addr);
                br[p * 2][0] = r[0]; br[p * 2][1] = r[1];
                br[p * 2 + 1][0] = r[2]; br[p * 2 + 1][1] = r[3];
            }
#pragma unroll
            for (int mt = 0; mt < 4; mt++)
#pragma unroll
                for (int nt = 0; nt < 4; nt++)
                    mma16816(acc[mt][nt], ar[mt], br[nt]);
        }
        if (++buf == 3) buf = 0;
    }
#undef PREFETCH

    // ---- epilogue ----
    const int lrow = lid >> 2;           // 0..7
    const int lcol = (lid & 3) * 2;      // 0,2,4,6
#pragma unroll
    for (int mt = 0; mt < 4; mt++) {
        const int gm = m0 + mbase + mt * 16 + lrow;
#pragma unroll
        for (int nt = 0; nt < 4; nt++) {
            const int gn = n0 + nbase + nt * 8 + lcol;
            if (MODE == 0) {
                const float b0 = bias[gn], b1 = bias[gn + 1];
                float2 v0 = {acc[mt][nt][0] + b0, acc[mt][nt][1] + b1};
                float2 v1 = {acc[mt][nt][2] + b0, acc[mt][nt][3] + b1};
                *(float2*)&C[(size_t)gm * D_MODEL + gn] = v0;
                *(float2*)&C[(size_t)(gm + 8) * D_MODEL + gn] = v1;
            } else {
                // QKV scatter: Q -> g_q, K/V -> present tail of d_out (KV)
#pragma unroll
                for (int e = 0; e < 4; e++) {
                    const int row = gm + (e >> 1) * 8;
                    const int f   = gn + (e & 1);
                    const float v = acc[mt][nt][e] + bias[f];
                    const int bb = row >> 11, s = row & 2047;
                    const int sec = f >> 10, fr = f & 1023;
                    const int h = fr >> 6, dd = fr & 63;
                    if (sec == 0)
                        g_q[(((size_t)bb * NH + h) * S_LEN + s) * HD + dd] = v;
                    else
                        KV[((((size_t)bb * 2 + (sec - 1)) * NH + h) * S_LEN + s) * HD + dd] = v;
                }
            }
        }
    }
}

// ---------------- sliding-window attention ----------------
// Reads K/V from the `present` tail of d_out; writes split bf16 directly
// into g_ahat (fuses the former convA(g_a) pass).
#define ATTN_SMEM_FLOATS (2 * 64 * 65 + 64 * 321 + 64)
#define ATTN_SMEM_BYTES  (ATTN_SMEM_FLOATS * 4)

__global__ __launch_bounds__(256) void attn_k(const float* __restrict__ KV)
{
    extern __shared__ float sm[];
    float (*Qs)[65]  = (float(*)[65])sm;
    float (*Ks)[65]  = (float(*)[65])(sm + 64 * 65);
    float (*Ss)[321] = (float(*)[321])(sm + 2 * 64 * 65);
    float* rinv      = sm + 2 * 64 * 65 + 64 * 321;

    const int bid = blockIdx.x;
    const int qt = bid & 31;
    const int h  = (bid >> 5) & 15;
    const int b  = bid >> 9;
    const int qs = qt * 64;

    const int tid = threadIdx.x;
    const int tx = tid & 15;
    const int ty = tid >> 4;
    const float scale = 0.125f;

    const float* Qg = g_q + (((size_t)b * NH + h) * S_LEN) * HD;
    const float* Kg = KV + ((((size_t)b * 2 + 0) * NH + h) * S_LEN) * HD;
    const float* Vg = KV + ((((size_t)b * 2 + 1) * NH + h) * S_LEN) * HD;

    for (int idx = tid; idx < 64 * 64; idx += 256) {
        const int i = idx >> 6, d = idx & 63;
        Qs[i][d] = Qg[(size_t)(qs + i) * HD + d] * scale;
    }

    for (int kt = 0; kt < 5; kt++) {
        const int ks = qs - 256 + kt * 64;
        if (ks + 64 <= 0) {
            for (int idx = tid; idx < 64 * 64; idx += 256)
                Ss[idx >> 6][kt * 64 + (idx & 63)] = -1e30f;
            continue;
        }
        __syncthreads();
        for (int idx = tid; idx < 64 * 64; idx += 256) {
            const int j = idx >> 6, d = idx & 63;
            const int gj = ks + j;
            Ks[j][d] = (gj >= 0) ? Kg[(size_t)gj * HD + d] : 0.f;
        }
        __syncthreads();

        float s[4][4];
#pragma unroll
        for (int r = 0; r < 4; r++)
#pragma unroll
            for (int c = 0; c < 4; c++) s[r][c] = 0.f;
        const int i0 = ty * 4, j0 = tx * 4;
#pragma unroll 8
        for (int d = 0; d < 64; d++) {
            float q[4], kk[4];
#pragma unroll
            for (int r = 0; r < 4; r++) q[r] = Qs[i0 + r][d];
#pragma unroll
            for (int c = 0; c < 4; c++) kk[c] = Ks[j0 + c][d];
#pragma unroll
            for (int r = 0; r < 4; r++)
#pragma unroll
                for (int c = 0; c < 4; c++) s[r][c] += q[r] * kk[c];
        }
#pragma unroll
        for (int r = 0; r < 4; r++) {
            const int gi = qs + i0 + r;
#pragma unroll
            for (int c = 0; c < 4; c++) {
                const int gj = ks + j0 + c;
                const bool ok = (gj >= 0) && (gj <= gi) && (gj > gi - WINDOW);
                Ss[i0 + r][kt * 64 + j0 + c] = ok ? s[r][c] : -1e30f;
            }
        }
    }
    __syncthreads();

    if (tid < 64) {
        float mx = -1e30f;
        for (int c = 0; c < 320; c++) mx = fmaxf(mx, Ss[tid][c]);
        float sum = 0.f;
        for (int c = 0; c < 320; c++) {
            const float e = __expf(Ss[tid][c] - mx);
            Ss[tid][c] = e;
            sum += e;
        }
        rinv[tid] = 1.f / sum;
    }

    float o[4][4];
#pragma unroll
    for (int r = 0; r < 4; r++)
#pragma unroll
        for (int c = 0; c < 4; c++) o[r][c] = 0.f;
    const int i0 = ty * 4, d0 = tx * 4;

    for (int kt = 0; kt < 5; kt++) {
        const int ks = qs - 256 + kt * 64;
        if (ks + 64 <= 0) continue;
        __syncthreads();
        for (int idx = tid; idx < 64 * 64; idx += 256) {
            const int j = idx >> 6, d = idx & 63;
            const int gj = ks + j;
            Ks[j][d] = (gj >= 0) ? Vg[(size_t)gj * HD + d] : 0.f;
        }
        __syncthreads();
#pragma unroll 8
        for (int j = 0; j < 64; j++) {
            float p[4], v[4];
#pragma unroll
            for (int r = 0; r < 4; r++) p[r] = Ss[i0 + r][kt * 64 + j];
#pragma unroll
            for (int c = 0; c < 4; c++) v[c] = Ks[j][d0 + c];
#pragma unroll
            for (int r = 0; r < 4; r++)
#pragma unroll
                for (int c = 0; c < 4; c++) o[r][c] += p[r] * v[c];
        }
    }

    // fused epilogue: write hi/hi/lo split bf16 straight into g_ahat
#pragma unroll
    for (int r = 0; r < 4; r++) {
        const float ri = rinv[i0 + r];
        const size_t m = (size_t)b * S_LEN + qs + i0 + r;
        __nv_bfloat16* row = g_ahat + m * KEFF;
        const int k = h * HD + d0;
#pragma unroll
        for (int c = 0; c < 4; c++) {
            const float v = o[r][c] * ri;
            const __nv_bfloat16 hi = __float2bfloat16(v);
            const __nv_bfloat16 lo = __float2bfloat16(v - __bfloat162float(hi));
            row[k + c] = hi;
            row[1024 + k + c] = hi;
            row[2048 + k + c] = lo;
        }
    }
}

// ---------------------------------------------------------------------------
extern "C" void kernel_launch(void* const* d_in, const int* in_sizes, int n_in,
                              void* d_out, int out_size)
{
    const float* x      = (const float*)d_in[0];
    const float* w_attn = (const float*)d_in[1];
    const float* b_attn = (const float*)d_in[2];
    const float* w_proj = (const float*)d_in[3];
    const float* b_proj = (const float*)d_in[4];
    float* out = (float*)d_out;
    float* kv  = out + OUT_ELEMS;   // `present` tail of the flattened output

    cudaFuncSetAttribute(attn_k, cudaFuncAttributeMaxDynamicSharedMemorySize, ATTN_SMEM_BYTES);
    cudaFuncSetAttribute(gemm_mma<0>, cudaFuncAttributeMaxDynamicSharedMemorySize, GEMM_SMEM);
    cudaFuncSetAttribute(gemm_mma<1>, cudaFuncAttributeMaxDynamicSharedMemorySize, GEMM_SMEM);

    __nv_bfloat16 *xhat, *ahat, *wat, *wpt;
    cudaGetSymbolAddress((void**)&xhat, g_xhat);
    cudaGetSymbolAddress((void**)&ahat, g_ahat);
    cudaGetSymbolAddress((void**)&wat,  g_wat);
    cudaGetSymbolAddress((void**)&wpt,  g_wpt);

    // 1) split conversions of inputs
    convA_k<<<(TOKENS * 1024 + 255) / 256, 256>>>(x, xhat, TOKENS * 1024);
    {
        dim3 blk(32, 32);
        convBt_k<<<dim3(3 * D_MODEL / 32, D_MODEL / 32), blk>>>(w_attn, wat, 3 * D_MODEL);
        convBt_k<<<dim3(D_MODEL / 32, D_MODEL / 32),     blk>>>(w_proj, wpt, D_MODEL);
    }

    // 2) QKV projection: Q -> g_q, K/V -> present tail of d_out
    gemm_mma<1><<<dim3(3 * D_MODEL / 128, TOKENS / 128), 256, GEMM_SMEM>>>(
        xhat, wat, b_attn, nullptr, kv);

    // 3) sliding-window attention (reads KV from out tail) -> g_ahat (split bf16)
    attn_k<<<BATCH * NH * (S_LEN / 64), 256, ATTN_SMEM_BYTES>>>(kv);

    // 4) output projection -> d_out head
    gemm_mma<0><<<dim3(D_MODEL / 128, TOKENS / 128), 256, GEMM_SMEM>>>(
        ahat, wpt, b_proj, out, nullptr);
}